// round 1
// baseline (speedup 1.0000x reference)
#include <cuda_runtime.h>

#define BB 2
#define TT 4096
#define CC 128
#define HH 8
#define DD 16
#define NT (BB*TT)        // 8192 rows

// ---------------- scratch (no allocations allowed) ----------------
__device__ float g_qkv[3ull * BB * HH * TT * DD];   // [mat][b][h][t][d], 12.6 MB
__device__ float g_att[(size_t)BB * TT * CC];       // [b][t][h*16+d],     4 MB

__device__ __forceinline__ float fast_exp2(float x) {
    float y;
    asm("ex2.approx.ftz.f32 %0, %1;" : "=f"(y) : "f"(x));
    return y;
}

// =================================================================
// Kernel 1: QKV projection. out[m,n] = sum_k x[m,k]*W[n,k]
// Block tile 64(m) x 64(n), K=128 in 32-tiles. 256 threads, 4x4 per thread.
// grid = (NT/64, 6): y/2 -> matrix (0=Q,1=K,2=V), y&1 -> n-half.
// Q gets 0.25 * log2(e) folded in (softmax scale in base-2 domain).
// =================================================================
__global__ __launch_bounds__(256) void qkv_kernel(
    const float* __restrict__ x,
    const float* __restrict__ Wq,
    const float* __restrict__ Wk,
    const float* __restrict__ Wv)
{
    __shared__ float As[32][64];
    __shared__ float Bs[32][64];
    const int tid  = threadIdx.x;
    const int m0   = blockIdx.x * 64;
    const int mat  = blockIdx.y >> 1;
    const int nb   = (blockIdx.y & 1) * 64;
    const float* W = (mat == 0) ? Wq : (mat == 1 ? Wk : Wv);
    const int tx = tid & 15, ty = tid >> 4;

    float acc[4][4] = {};

    const int r  = tid >> 2;           // 0..63
    const int c4 = (tid & 3) * 8;      // 0,8,16,24

    for (int k0 = 0; k0 < CC; k0 += 32) {
        float4 a0 = *(const float4*)&x[(size_t)(m0 + r) * CC + k0 + c4];
        float4 a1 = *(const float4*)&x[(size_t)(m0 + r) * CC + k0 + c4 + 4];
        As[c4+0][r]=a0.x; As[c4+1][r]=a0.y; As[c4+2][r]=a0.z; As[c4+3][r]=a0.w;
        As[c4+4][r]=a1.x; As[c4+5][r]=a1.y; As[c4+6][r]=a1.z; As[c4+7][r]=a1.w;
        float4 b0 = *(const float4*)&W[(size_t)(nb + r) * CC + k0 + c4];
        float4 b1 = *(const float4*)&W[(size_t)(nb + r) * CC + k0 + c4 + 4];
        Bs[c4+0][r]=b0.x; Bs[c4+1][r]=b0.y; Bs[c4+2][r]=b0.z; Bs[c4+3][r]=b0.w;
        Bs[c4+4][r]=b1.x; Bs[c4+5][r]=b1.y; Bs[c4+6][r]=b1.z; Bs[c4+7][r]=b1.w;
        __syncthreads();
        #pragma unroll
        for (int kk = 0; kk < 32; kk++) {
            float4 a = *(const float4*)&As[kk][ty * 4];
            float4 b = *(const float4*)&Bs[kk][tx * 4];
            float av[4] = {a.x, a.y, a.z, a.w};
            float bv[4] = {b.x, b.y, b.z, b.w};
            #pragma unroll
            for (int i = 0; i < 4; i++)
                #pragma unroll
                for (int j = 0; j < 4; j++)
                    acc[i][j] += av[i] * bv[j];
        }
        __syncthreads();
    }

    const float qs = 0.25f * 1.4426950408889634f;  // D^-0.5 * log2(e)
    #pragma unroll
    for (int i = 0; i < 4; i++) {
        const int m = m0 + ty * 4 + i;
        const int b = m >> 12;          // /TT
        const int t = m & (TT - 1);
        #pragma unroll
        for (int j = 0; j < 4; j++) {
            const int n = nb + tx * 4 + j;
            const int h = n >> 4, d = n & 15;
            float v = acc[i][j];
            if (mat == 0) v *= qs;
            g_qkv[((((size_t)mat * BB + b) * HH + h) * TT + t) * DD + d] = v;
        }
    }
}

// =================================================================
// Kernel 2: causal flash attention, fp32.
// grid = (T/128, H, B), block = 128 threads, one query row per thread.
// Online softmax in base-2 domain (scale folded into Q).
// =================================================================
__global__ __launch_bounds__(128) void attn_kernel()
{
    __shared__ float4 Ks[128][4];
    __shared__ float4 Vs[128][4];

    const int tid = threadIdx.x;
    const int i = (int)(gridDim.x - 1u - blockIdx.x);  // big tiles first
    const int h = blockIdx.y;
    const int b = blockIdx.z;

    const size_t matsz = (size_t)BB * HH * TT * DD;
    const float* Qg = &g_qkv[0 * matsz + (((size_t)b * HH + h) * TT) * DD];
    const float* Kg = &g_qkv[1 * matsz + (((size_t)b * HH + h) * TT) * DD];
    const float* Vg = &g_qkv[2 * matsz + (((size_t)b * HH + h) * TT) * DD];

    // load this thread's query row (16 floats, already scaled)
    float4 q0, q1, q2, q3;
    {
        const float4* qp = (const float4*)&Qg[(size_t)(i * 128 + tid) * DD];
        q0 = qp[0]; q1 = qp[1]; q2 = qp[2]; q3 = qp[3];
    }

    float o[16];
    #pragma unroll
    for (int d = 0; d < 16; d++) o[d] = 0.0f;
    float mrun = -1e30f;
    float l = 0.0f;

    for (int j = 0; j <= i; j++) {
        // stage K/V tiles (contiguous 2048 floats each)
        {
            float4* kd = &Ks[0][0];
            float4* vd = &Vs[0][0];
            const float4* ks = (const float4*)&Kg[(size_t)j * 128 * DD];
            const float4* vs = (const float4*)&Vg[(size_t)j * 128 * DD];
            #pragma unroll
            for (int it = 0; it < 4; it++) {
                kd[tid + it * 128] = ks[tid + it * 128];
                vd[tid + it * 128] = vs[tid + it * 128];
            }
        }
        __syncthreads();

        const bool diag = (j == i);
        for (int c = 0; c < 8; c++) {
            const int s0 = c * 16;
            if (diag && s0 > tid) break;     // rest of tile fully masked for this row

            float sc[16];
            #pragma unroll
            for (int u = 0; u < 16; u++) {
                float4 k0 = Ks[s0 + u][0], k1 = Ks[s0 + u][1];
                float4 k2 = Ks[s0 + u][2], k3 = Ks[s0 + u][3];
                float s = q0.x*k0.x + q0.y*k0.y + q0.z*k0.z + q0.w*k0.w;
                s += q1.x*k1.x + q1.y*k1.y + q1.z*k1.z + q1.w*k1.w;
                s += q2.x*k2.x + q2.y*k2.y + q2.z*k2.z + q2.w*k2.w;
                s += q3.x*k3.x + q3.y*k3.y + q3.z*k3.z + q3.w*k3.w;
                sc[u] = s;
            }
            if (diag) {
                #pragma unroll
                for (int u = 0; u < 16; u++)
                    if (s0 + u > tid) sc[u] = -1e30f;
            }
            float cm = sc[0];
            #pragma unroll
            for (int u = 1; u < 16; u++) cm = fmaxf(cm, sc[u]);
            const float nm = fmaxf(mrun, cm);
            const float corr = fast_exp2(mrun - nm);
            mrun = nm;
            l *= corr;
            #pragma unroll
            for (int d = 0; d < 16; d++) o[d] *= corr;
            #pragma unroll
            for (int u = 0; u < 16; u++) {
                const float p = fast_exp2(sc[u] - mrun);
                l += p;
                float4 v0 = Vs[s0 + u][0], v1 = Vs[s0 + u][1];
                float4 v2 = Vs[s0 + u][2], v3 = Vs[s0 + u][3];
                o[0]  += p * v0.x; o[1]  += p * v0.y; o[2]  += p * v0.z; o[3]  += p * v0.w;
                o[4]  += p * v1.x; o[5]  += p * v1.y; o[6]  += p * v1.z; o[7]  += p * v1.w;
                o[8]  += p * v2.x; o[9]  += p * v2.y; o[10] += p * v2.z; o[11] += p * v2.w;
                o[12] += p * v3.x; o[13] += p * v3.y; o[14] += p * v3.z; o[15] += p * v3.w;
            }
        }
        __syncthreads();
    }

    const float inv = 1.0f / l;
    float* outp = &g_att[((size_t)b * TT + i * 128 + tid) * CC + h * DD];
    #pragma unroll
    for (int d4 = 0; d4 < 4; d4++) {
        float4 w;
        w.x = o[d4*4+0] * inv; w.y = o[d4*4+1] * inv;
        w.z = o[d4*4+2] * inv; w.w = o[d4*4+3] * inv;
        ((float4*)outp)[d4] = w;
    }
}

// =================================================================
// Kernel 3: output projection: out = attn @ Wp.T + bp
// Same tiling as kernel 1; grid = (NT/64, 2).
// =================================================================
__global__ __launch_bounds__(256) void proj_kernel(
    const float* __restrict__ Wp,
    const float* __restrict__ bp,
    float* __restrict__ out)
{
    __shared__ float As[32][64];
    __shared__ float Bs[32][64];
    const int tid = threadIdx.x;
    const int m0  = blockIdx.x * 64;
    const int nb  = blockIdx.y * 64;
    const int tx = tid & 15, ty = tid >> 4;

    float acc[4][4] = {};
    const int r  = tid >> 2;
    const int c4 = (tid & 3) * 8;

    for (int k0 = 0; k0 < CC; k0 += 32) {
        float4 a0 = *(const float4*)&g_att[(size_t)(m0 + r) * CC + k0 + c4];
        float4 a1 = *(const float4*)&g_att[(size_t)(m0 + r) * CC + k0 + c4 + 4];
        As[c4+0][r]=a0.x; As[c4+1][r]=a0.y; As[c4+2][r]=a0.z; As[c4+3][r]=a0.w;
        As[c4+4][r]=a1.x; As[c4+5][r]=a1.y; As[c4+6][r]=a1.z; As[c4+7][r]=a1.w;
        float4 b0 = *(const float4*)&Wp[(size_t)(nb + r) * CC + k0 + c4];
        float4 b1 = *(const float4*)&Wp[(size_t)(nb + r) * CC + k0 + c4 + 4];
        Bs[c4+0][r]=b0.x; Bs[c4+1][r]=b0.y; Bs[c4+2][r]=b0.z; Bs[c4+3][r]=b0.w;
        Bs[c4+4][r]=b1.x; Bs[c4+5][r]=b1.y; Bs[c4+6][r]=b1.z; Bs[c4+7][r]=b1.w;
        __syncthreads();
        #pragma unroll
        for (int kk = 0; kk < 32; kk++) {
            float4 a = *(const float4*)&As[kk][ty * 4];
            float4 b = *(const float4*)&Bs[kk][tx * 4];
            float av[4] = {a.x, a.y, a.z, a.w};
            float bv[4] = {b.x, b.y, b.z, b.w};
            #pragma unroll
            for (int i = 0; i < 4; i++)
                #pragma unroll
                for (int j = 0; j < 4; j++)
                    acc[i][j] += av[i] * bv[j];
        }
        __syncthreads();
    }

    #pragma unroll
    for (int i = 0; i < 4; i++) {
        const int m = m0 + ty * 4 + i;
        #pragma unroll
        for (int j = 0; j < 4; j++) {
            const int n = nb + tx * 4 + j;
            out[(size_t)m * CC + n] = acc[i][j] + bp[n];
        }
    }
}

// =================================================================
extern "C" void kernel_launch(void* const* d_in, const int* in_sizes, int n_in,
                              void* d_out, int out_size)
{
    const float* x  = (const float*)d_in[0];
    const float* Wk = (const float*)d_in[1];
    const float* Wq = (const float*)d_in[2];
    const float* Wv = (const float*)d_in[3];
    const float* Wp = (const float*)d_in[4];
    const float* bp = (const float*)d_in[5];
    float* out = (float*)d_out;

    qkv_kernel<<<dim3(NT / 64, 6), 256>>>(x, Wq, Wk, Wv);
    attn_kernel<<<dim3(TT / 128, HH, BB), 128>>>();
    proj_kernel<<<dim3(NT / 64, 2), 256>>>(Wp, bp, out);
}